// round 9
// baseline (speedup 1.0000x reference)
#include <cuda_runtime.h>
#include <math.h>

#define NN 16384
#define DD 64
#define KK 3
#define G 16
#define CELLS (G * G * G)   // 4096
#define CAP 48              // bucket capacity (P(overflow) ~ 1e-40 for Poisson(4))
#define FULLM 0xFFFFFFFFu

// ---------------- scratch (device globals, no allocation) ----------------
__device__ float g_x[NN * DD];      // features after LN2
__device__ float g_xnorm[NN];       // row L2 norms
__device__ int   g_knn[NN * KK];
__device__ float g_ew[NN * KK];
__device__ float g_dis[NN];         // rsqrt(deg)
__device__ float g_t[NN * DD];      // relu(LN(gcn1 out))

__device__ int    g_cnt[CELLS];
__device__ float4 g_bkt[CELLS * CAP];   // (x, y, z, idx-as-bits)

__device__ __forceinline__ float wsum(float v) {
    #pragma unroll
    for (int o = 16; o > 0; o >>= 1) v += __shfl_xor_sync(FULLM, v, o);
    return v;
}

__device__ __forceinline__ int cell_of(float x, float y, float z) {
    int cx = min(G - 1, max(0, (int)(x * (float)G)));
    int cy = min(G - 1, max(0, (int)(y * (float)G)));
    int cz = min(G - 1, max(0, (int)(z * (float)G)));
    return (cz * G + cy) * G + cx;
}

// exact reference arithmetic
__device__ __forceinline__ float sq_exact(float x, float y, float z) {
    return __fadd_rn(__fadd_rn(__fmul_rn(x, x), __fmul_rn(y, y)), __fmul_rn(z, z));
}
__device__ __forceinline__ float dist_exact(float qx, float qy, float qz, float qsq,
                                            float px, float py, float pz, float psq) {
    float dot = __fmaf_rn(qz, pz, __fmaf_rn(qy, py, __fmul_rn(qx, px)));
    return __fmaf_rn(-2.0f, dot, __fadd_rn(qsq, psq));
}

__device__ __forceinline__ bool knn_lt(float d, int i, float D, int I) {
    return d < D || (d == D && i < I);
}
__device__ __forceinline__ void insert3(float d, int j,
                                        float& d0, float& d1, float& d2,
                                        int& i0, int& i1, int& i2) {
    if (knn_lt(d, j, d2, i2)) {
        if (knn_lt(d, j, d1, i1)) {
            if (knn_lt(d, j, d0, i0)) { d2 = d1; i2 = i1; d1 = d0; i1 = i0; d0 = d; i0 = j; }
            else                      { d2 = d1; i2 = i1; d1 = d;  i1 = j; }
        } else                        { d2 = d;  i2 = j; }
    }
}

// order-preserving float->u32 (lexicographic (d, idx) as one u64 key)
__device__ __forceinline__ unsigned int f2ord(float f) {
    unsigned int u = __float_as_uint(f);
    return (u & 0x80000000u) ? ~u : (u | 0x80000000u);
}
__device__ __forceinline__ float ord2f(unsigned int o) {
    unsigned int u = (o & 0x80000000u) ? (o & 0x7FFFFFFFu) : ~o;
    return __uint_as_float(u);
}
__device__ __forceinline__ unsigned long long packdi(float d, int i) {
    return ((unsigned long long)f2ord(d) << 32) | (unsigned int)i;
}

// serial global ring walk (rare fallback)
__device__ void ring_walk(int q, float qx, float qy, float qz, float qsq,
                          int cx, int cy, int cz, int rstart,
                          float& d0, float& d1, float& d2,
                          int& i0, int& i1, int& i2) {
    const float h = 1.0f / (float)G;
    for (int r = rstart; ; r++) {
        int z0 = max(cz - r, 0), z1 = min(cz + r, G - 1);
        int y0 = max(cy - r, 0), y1 = min(cy + r, G - 1);
        int x0 = max(cx - r, 0), x1 = min(cx + r, G - 1);
        for (int zz = z0; zz <= z1; zz++)
            for (int yy = y0; yy <= y1; yy++)
                for (int xx = x0; xx <= x1; xx++) {
                    int ma = max(abs(xx - cx), max(abs(yy - cy), abs(zz - cz)));
                    if (ma != r) continue;
                    int c = (zz * G + yy) * G + xx;
                    int cnt = min(g_cnt[c], CAP);
                    const float4* bp = &g_bkt[c * CAP];
                    for (int t = 0; t < cnt; t++) {
                        float4 p = bp[t];
                        int j = __float_as_int(p.w);
                        if (j == q) continue;
                        float d = dist_exact(qx, qy, qz, qsq, p.x, p.y, p.z,
                                             sq_exact(p.x, p.y, p.z));
                        insert3(d, j, d0, d1, d2, i0, i1, i2);
                    }
                }
        bool full = (x0 == 0 && x1 == G - 1 && y0 == 0 && y1 == G - 1 &&
                     z0 == 0 && z1 == G - 1);
        if (full) return;
        if (i2 != 0x7fffffff) {
            float m = INFINITY;
            if (cx - r > 0)     m = fminf(m, qx - (float)(cx - r) * h);
            if (cx + r < G - 1) m = fminf(m, (float)(cx + r + 1) * h - qx);
            if (cy - r > 0)     m = fminf(m, qy - (float)(cy - r) * h);
            if (cy + r < G - 1) m = fminf(m, (float)(cy + r + 1) * h - qy);
            if (cz - r > 0)     m = fminf(m, qz - (float)(cz - r) * h);
            if (cz + r < G - 1) m = fminf(m, (float)(cz + r + 1) * h - qz);
            if (m * m > d2 + 1e-5f) return;   // conservative: rounding skew <= ~3e-6
        }
    }
}

// ---------------- grid zero ----------------
__global__ void grid_zero() {
    g_cnt[blockIdx.x * 256 + threadIdx.x] = 0;
}

// ---------------- merged: grid_build (blocks 0..63) + LN chain ----------------
__global__ void build_ln(const float* __restrict__ coords,
                         const float* __restrict__ in,
                         const float* __restrict__ g1, const float* __restrict__ b1,
                         const float* __restrict__ g2, const float* __restrict__ b2) {
    if (blockIdx.x < NN / 256) {
        int i = blockIdx.x * 256 + threadIdx.x;
        float x = coords[3 * i], y = coords[3 * i + 1], z = coords[3 * i + 2];
        int c = cell_of(x, y, z);
        int pos = atomicAdd(&g_cnt[c], 1);
        if (pos < CAP) g_bkt[c * CAP + pos] = make_float4(x, y, z, __int_as_float(i));
        return;
    }
    int bb = blockIdx.x - NN / 256;
    int lane = threadIdx.x & 31;
    int ty = threadIdx.x >> 5;
    int i = bb * 8 + ty;
    const float* row = in + (size_t)i * DD;
    float a0 = row[lane], a1 = row[lane + 32];

    float m = wsum(a0 + a1) * (1.0f / 64.0f);
    float d0 = a0 - m, d1 = a1 - m;
    float v = wsum(d0 * d0 + d1 * d1) * (1.0f / 64.0f);
    float inv = rsqrtf(v + 1e-5f);
    float y0 = d0 * inv * g1[lane] + b1[lane];
    float y1 = d1 * inv * g1[lane + 32] + b1[lane + 32];

    y0 *= 2.0f; y1 *= 2.0f;   // x = x + x

    m = wsum(y0 + y1) * (1.0f / 64.0f);
    d0 = y0 - m; d1 = y1 - m;
    v = wsum(d0 * d0 + d1 * d1) * (1.0f / 64.0f);
    inv = rsqrtf(v + 1e-5f);
    float x0 = d0 * inv * g2[lane] + b2[lane];
    float x1 = d1 * inv * g2[lane + 32] + b2[lane + 32];

    g_x[(size_t)i * DD + lane] = x0;
    g_x[(size_t)i * DD + lane + 32] = x1;

    float s = wsum(x0 * x0 + x1 * x1);
    if (lane == 0) g_xnorm[i] = fmaxf(sqrtf(s), 1e-8f);
}

// ---------------- K2: KNN (candidate-flattened, warp/query) + fused edge weights --
__global__ void knn_ew(const float* __restrict__ coords) {
    int q = (blockIdx.x * blockDim.x + threadIdx.x) >> 5;
    int lane = threadIdx.x & 31;

    float qx = coords[3 * q], qy = coords[3 * q + 1], qz = coords[3 * q + 2];
    float qsq = sq_exact(qx, qy, qz);
    int cx = min(G - 1, max(0, (int)(qx * (float)G)));
    int cy = min(G - 1, max(0, (int)(qy * (float)G)));
    int cz = min(G - 1, max(0, (int)(qz * (float)G)));
    const float h = 1.0f / (float)G;

    // lane -> one of the 27 ring<=1 cells; OOB => cnt 0
    int cnt = 0, cell = 0;
    if (lane < 27) {
        int dz = lane / 9 - 1, dy = (lane % 9) / 3 - 1, dx = lane % 3 - 1;
        int xx = cx + dx, yy = cy + dy, zz = cz + dz;
        if (xx >= 0 && xx < G && yy >= 0 && yy < G && zz >= 0 && zz < G) {
            cell = (zz * G + yy) * G + xx;
            cnt = min(g_cnt[cell], CAP);
        }
    }
    // warp inclusive scan -> exclusive prefix
    int inc = cnt;
    #pragma unroll
    for (int off = 1; off < 32; off <<= 1) {
        int v = __shfl_up_sync(FULLM, inc, off);
        if (lane >= off) inc += v;
    }
    int exc = inc - cnt;
    int total = __shfl_sync(FULLM, inc, 31);

    // stride flattened candidates; all lanes stay converged (uniform iteration count)
    float d0 = INFINITY, d1 = INFINITY, d2 = INFINITY;
    int i0 = 0x7fffffff, i1 = 0x7fffffff, i2 = 0x7fffffff;
    int nIter = (total + 31) >> 5;
    for (int it = 0; it < nIter; it++) {
        int t = it * 32 + lane;
        bool valid = t < total;
        int ts = valid ? t : total - 1;   // safe index for the search
        int lo = 0, hi = 26;
        #pragma unroll
        for (int s = 0; s < 5; s++) {     // binary search: largest seg with exc[seg] <= ts
            int mid = (lo + hi + 1) >> 1;
            int pm = __shfl_sync(FULLM, exc, mid);
            bool ge = (pm <= ts);
            lo = ge ? mid : lo;
            hi = ge ? hi : mid - 1;
        }
        int c    = __shfl_sync(FULLM, cell, lo);
        int base = __shfl_sync(FULLM, exc, lo);
        if (valid) {
            float4 p = g_bkt[c * CAP + (ts - base)];
            int j = __float_as_int(p.w);
            if (j != q) {
                float d = dist_exact(qx, qy, qz, qsq, p.x, p.y, p.z,
                                     sq_exact(p.x, p.y, p.z));
                insert3(d, j, d0, d1, d2, i0, i1, i2);
            }
        }
    }

    // 3 extract-min rounds on packed (ord(d), idx) keys (exact lexicographic order)
    unsigned long long k0 = packdi(d0, i0), k1 = packdi(d1, i1), k2 = packdi(d2, i2);
    float outD[3]; int outI[3];
    #pragma unroll
    for (int r = 0; r < 3; r++) {
        unsigned long long m = k0;
        #pragma unroll
        for (int off = 16; off >= 1; off >>= 1) {
            unsigned long long o = __shfl_xor_sync(FULLM, m, off);
            if (o < m) m = o;
        }
        outD[r] = ord2f((unsigned int)(m >> 32));
        outI[r] = (int)(unsigned int)(m & 0xFFFFFFFFu);
        if (k0 == m) { k0 = k1; k1 = k2; k2 = 0xFFFFFFFFFFFFFFFFull; }
    }

    // conservative stopping bound at r = 1 (uniform across warp)
    {
        float m = INFINITY;
        if (cx - 1 > 0)     m = fminf(m, qx - (float)(cx - 1) * h);
        if (cx + 1 < G - 1) m = fminf(m, (float)(cx + 2) * h - qx);
        if (cy - 1 > 0)     m = fminf(m, qy - (float)(cy - 1) * h);
        if (cy + 1 < G - 1) m = fminf(m, (float)(cy + 2) * h - qy);
        if (cz - 1 > 0)     m = fminf(m, qz - (float)(cz - 1) * h);
        if (cz + 1 < G - 1) m = fminf(m, (float)(cz + 2) * h - qz);
        bool ok = (outI[2] != 0x7fffffff) && (m * m > outD[2] + 1e-5f);
        if (!ok) {           // rare (~1e-4): serial walk on lane 0 from r=2
            if (lane == 0) {
                float f0 = outD[0], f1 = outD[1], f2 = outD[2];
                int   j0 = outI[0], j1 = outI[1], j2 = outI[2];
                ring_walk(q, qx, qy, qz, qsq, cx, cy, cz, 2, f0, f1, f2, j0, j1, j2);
                outI[0] = j0; outI[1] = j1; outI[2] = j2;
            }
            #pragma unroll
            for (int r = 0; r < 3; r++) outI[r] = __shfl_sync(FULLM, outI[r], 0);
        }
    }

    // ---- fused edge weights: sigmoid(cosine), degree, dis ----
    float xi0 = g_x[(size_t)q * DD + lane];
    float xi1 = g_x[(size_t)q * DD + lane + 32];
    float ni = g_xnorm[q];
    float deg = 1.0f;
    float ews[KK];
    #pragma unroll
    for (int k = 0; k < KK; k++) {
        int nb = outI[k];
        float dot = wsum(xi0 * g_x[(size_t)nb * DD + lane] +
                         xi1 * g_x[(size_t)nb * DD + lane + 32]);
        float z = dot / (g_xnorm[nb] * ni);
        float e = 1.0f / (1.0f + expf(-z));
        ews[k] = e;
        deg += e;
    }
    float dis = rsqrtf(deg);
    if (lane == 0) {
        #pragma unroll
        for (int k = 0; k < KK; k++) {
            g_knn[q * 3 + k] = outI[k];
            g_ew[q * 3 + k] = ews[k];
        }
        g_dis[q] = dis;
    }
}

// ---------------- K4/K5: fused GCN (32 rows/block, col-pair per thread) ----------------
template <int EPI>
__global__ void gcn_kernel(const float* __restrict__ W, const float* __restrict__ b,
                           const float* __restrict__ lng, const float* __restrict__ lnb,
                           float* __restrict__ out) {
    __shared__ float sW[DD * DD];
    __shared__ float sZ[8][DD];
    int tid = threadIdx.y * 32 + threadIdx.x;
    for (int k = tid; k < DD * DD; k += 256) sW[k] = W[k];
    __syncthreads();

    int lane = threadIdx.x;
    int ty = threadIdx.y;
    int c0 = 2 * lane;
    const float* xin = (EPI == 1) ? g_x : g_t;
    float2 bb = *(const float2*)&b[c0];

    #pragma unroll
    for (int rb = 0; rb < 4; rb++) {
        int i = blockIdx.x * 32 + rb * 8 + ty;

        float dii = g_dis[i];
        float cs = dii * dii;
        float2 xi = *(const float2*)&xin[(size_t)i * DD + c0];
        float z0 = cs * xi.x, z1 = cs * xi.y;
        #pragma unroll
        for (int k = 0; k < KK; k++) {
            int nb = g_knn[i * 3 + k];
            float c = g_dis[nb] * g_ew[i * 3 + k] * dii;
            float2 xn = *(const float2*)&xin[(size_t)nb * DD + c0];
            z0 = fmaf(c, xn.x, z0);
            z1 = fmaf(c, xn.y, z1);
        }
        sZ[ty][c0] = z0;
        sZ[ty][c0 + 1] = z1;
        __syncwarp();

        float acc0 = 0.0f, acc1 = 0.0f;
        #pragma unroll
        for (int k = 0; k < DD; k++) {
            float zk = sZ[ty][k];
            float2 w = *(const float2*)&sW[k * DD + c0];
            acc0 = fmaf(zk, w.x, acc0);
            acc1 = fmaf(zk, w.y, acc1);
        }
        acc0 += bb.x;
        acc1 += bb.y;

        if (EPI == 1) {
            float m = wsum(acc0 + acc1) * (1.0f / 64.0f);
            float e0 = acc0 - m, e1 = acc1 - m;
            float v = wsum(e0 * e0 + e1 * e1) * (1.0f / 64.0f);
            float inv = rsqrtf(v + 1e-5f);
            float2 o;
            o.x = fmaxf(e0 * inv * lng[c0] + lnb[c0], 0.0f);
            o.y = fmaxf(e1 * inv * lng[c0 + 1] + lnb[c0 + 1], 0.0f);
            *(float2*)&g_t[(size_t)i * DD + c0] = o;
        } else {
            float2 xv = *(const float2*)&g_x[(size_t)i * DD + c0];
            float2 o;
            o.x = fmaf(2.0f, xv.x, acc0);
            o.y = fmaf(2.0f, xv.y, acc1);
            *(float2*)&out[(size_t)i * DD + c0] = o;
        }
        __syncwarp();
    }
}

// ---------------- launch ----------------
extern "C" void kernel_launch(void* const* d_in, const int* in_sizes, int n_in,
                              void* d_out, int out_size) {
    const float* feat   = (const float*)d_in[0];
    const float* coords = (const float*)d_in[4];
    const float* n1g = (const float*)d_in[5];
    const float* n1b = (const float*)d_in[6];
    const float* n2g = (const float*)d_in[7];
    const float* n2b = (const float*)d_in[8];
    const float* gng = (const float*)d_in[9];
    const float* gnb = (const float*)d_in[10];
    const float* W1  = (const float*)d_in[11];
    const float* b1  = (const float*)d_in[12];
    const float* W2  = (const float*)d_in[13];
    const float* b2  = (const float*)d_in[14];
    float* out = (float*)d_out;

    dim3 th(32, 8);
    grid_zero<<<CELLS / 256, 256>>>();
    build_ln<<<NN / 256 + NN / 8, 256>>>(coords, feat, n1g, n1b, n2g, n2b);
    knn_ew<<<NN * 32 / 256, 256>>>(coords);
    gcn_kernel<1><<<NN / 32, th>>>(W1, b1, gng, gnb, nullptr);
    gcn_kernel<2><<<NN / 32, th>>>(W2, b2, nullptr, nullptr, out);
}